// round 2
// baseline (speedup 1.0000x reference)
#include <cuda_runtime.h>
#include <cuda_bf16.h>
#include <math.h>

// ---------------- problem constants ----------------
#define TN   4096
#define DN   128
#define HN   512
#define EN   256
#define WN   4
#define G3H  1536

// scan config
#define NC   128      // persistent CTAs (all co-resident on 148 SMs)
#define NTH  256
#define CP   4        // H-columns owned per CTA (NC*CP = 512)

// ---------------- device scratch (static; no cudaMalloc) ----------------
__device__ float g_px [(size_t)TN * G3H];         // x@W + b
__device__ float g_pxa[(size_t)TN * HN];          // x@Wa + ba
__device__ float g_pxw[(size_t)TN * WN * G3H];    // emb[wid]@Ww + bw (active only)
__device__ float g_cw [WN * HN];                  // per-step c_w exchange
__device__ int   g_bar;                           // grid barrier counter
__device__ int   g_nact;                          // number of active (t,w)
__device__ int   g_gather [TN * WN];              // active -> word id (emb row)
__device__ int   g_scatter[TN * WN];              // active -> flat (t*WN+w)
__device__ unsigned char g_mask[TN * WN];         // decoded bool mask

__device__ __forceinline__ float sigmf(float v) { return 1.0f / (1.0f + expf(-v)); }

// ---------------- zero counters (every replay) ----------------
__global__ void zero_kernel() {
    g_bar = 0;
    g_nact = 0;
}

// ---------------- mask dtype detection + decode ----------------
// bool from the reference could arrive as uint8 (1B), int32 (4B) or float32 (4B).
// Inspect nonzero-byte residues of the first T*WN bytes (safe for every case):
//   uint8 0/1  -> nonzero bytes at all residues (mask ~27% dense)
//   int32 0/1  -> nonzero only at residue 0 (little-endian low byte)
//   float 1.0f -> nonzero only at residues 2,3 (0x80, 0x3F)
__global__ void mask_decode_kernel(const unsigned char* __restrict__ raw) {
    __shared__ int nz[4];
    int tid = threadIdx.x;
    if (tid < 4) nz[tid] = 0;
    __syncthreads();
    for (int i = tid; i < TN * WN; i += blockDim.x)
        if (raw[i]) atomicOr(&nz[i & 3], 1);
    __syncthreads();
    int mode;
    if (nz[0]) mode = (nz[1] | nz[2] | nz[3]) ? 0 : 1;   // 0=u8, 1=i32
    else       mode = (nz[2] | nz[3]) ? 2 : 0;           // 2=f32
    for (int i = tid; i < TN * WN; i += blockDim.x) {
        unsigned char m;
        if (mode == 0)      m = (raw[i] != 0);
        else if (mode == 1) m = (((const int*)raw)[i] != 0);
        else                m = (((const float*)raw)[i] != 0.0f);
        g_mask[i] = m;
    }
}

// ---------------- build compact active-word list ----------------
__global__ void build_active_kernel(const int* __restrict__ word_ids) {
    int i = blockIdx.x * blockDim.x + threadIdx.x;
    if (i < TN * WN && g_mask[i]) {
        int pos = atomicAdd(&g_nact, 1);
        g_gather[pos]  = word_ids[i];
        g_scatter[pos] = i;
    }
}

// ---------------- fp32 SGEMM: C = (gather?)A @ B + bias ----------------
// 64x64 tile, Ktile 16, 256 threads, 4x4 per thread.
// dst_sel: 0 -> g_px, 1 -> g_pxa, 2 -> g_pxw (scatter rows, gather A rows)
__global__ void __launch_bounds__(256) sgemm_kernel(
    const float* __restrict__ A, const float* __restrict__ B,
    const float* __restrict__ bias,
    int M, int N, int K, int use_gather, int dst_sel)
{
    __shared__ float As[16][68];
    __shared__ float Bs[16][68];

    float* C = (dst_sel == 0) ? g_px : (dst_sel == 1) ? g_pxa : g_pxw;
    int Meff = use_gather ? g_nact : M;
    int row0 = blockIdx.y * 64;
    int col0 = blockIdx.x * 64;
    if (row0 >= Meff) return;

    int tid = threadIdx.x;
    int tx = tid & 15, ty = tid >> 4;

    int arow_l = tid >> 2;
    int ak0    = (tid & 3) * 4;
    int arow_g = row0 + arow_l;
    bool a_ok  = (arow_g < Meff);
    const float* Arow = A;
    if (a_ok) {
        int r = use_gather ? g_gather[arow_g] : arow_g;
        Arow = A + (size_t)r * K;
    }
    int bk  = tid >> 4;
    int bc0 = (tid & 15) * 4;

    float acc[4][4];
    #pragma unroll
    for (int i = 0; i < 4; i++)
        #pragma unroll
        for (int j = 0; j < 4; j++) acc[i][j] = 0.0f;

    for (int k0 = 0; k0 < K; k0 += 16) {
        float4 av = make_float4(0.f, 0.f, 0.f, 0.f);
        if (a_ok) av = *reinterpret_cast<const float4*>(Arow + k0 + ak0);
        As[ak0 + 0][arow_l] = av.x;
        As[ak0 + 1][arow_l] = av.y;
        As[ak0 + 2][arow_l] = av.z;
        As[ak0 + 3][arow_l] = av.w;
        float4 bv = *reinterpret_cast<const float4*>(B + (size_t)(k0 + bk) * N + col0 + bc0);
        *reinterpret_cast<float4*>(&Bs[bk][bc0]) = bv;
        __syncthreads();
        #pragma unroll
        for (int kk = 0; kk < 16; kk++) {
            float4 a4 = *reinterpret_cast<const float4*>(&As[kk][ty * 4]);
            float4 b4 = *reinterpret_cast<const float4*>(&Bs[kk][tx * 4]);
            float aa[4] = {a4.x, a4.y, a4.z, a4.w};
            float bb[4] = {b4.x, b4.y, b4.z, b4.w};
            #pragma unroll
            for (int i = 0; i < 4; i++)
                #pragma unroll
                for (int j = 0; j < 4; j++)
                    acc[i][j] = fmaf(aa[i], bb[j], acc[i][j]);
        }
        __syncthreads();
    }
    #pragma unroll
    for (int i = 0; i < 4; i++) {
        int r = row0 + ty * 4 + i;
        if (r < Meff) {
            int cr = use_gather ? g_scatter[r] : r;
            float* Crow = C + (size_t)cr * N + col0 + tx * 4;
            #pragma unroll
            for (int j = 0; j < 4; j++)
                Crow[j] = acc[i][j] + bias[col0 + tx * 4 + j];
        }
    }
}

// ---------------- persistent lattice scan ----------------
// CTA n owns H-columns j0..j0+3. Per-CTA weight columns live in registers:
//   warps 0-2 : U   cols {q*512 + j0+k}, q = wid      (i,o,g gates)
//   warps 3-5 : Uw  cols {q*512 + j0+k}, q = wid-3    (f,i,g word gates)
//   warps 6-7 : Ua  cols {j0 + (wid-6)*2 + k}, k<2
// Two counter-based grid barriers per step.
__global__ void __launch_bounds__(NTH, 1) scan_kernel(
    const float* __restrict__ h0, const float* __restrict__ c0,
    const int* __restrict__ word_starts,
    const float* __restrict__ U, const float* __restrict__ Uw,
    const float* __restrict__ Ua, float* __restrict__ out)
{
    const int n    = blockIdx.x;
    const int tid  = threadIdx.x;
    const int wid  = tid >> 5;
    const int lane = tid & 31;
    const int j0   = n * CP;

    __shared__ float sh_h[HN];
    __shared__ float sh_hs[WN][HN];
    __shared__ float sh_cw[WN][HN];
    __shared__ float sh_px[3][CP];
    __shared__ float sh_pxa[CP];
    __shared__ float sh_pxw[WN][3][CP];
    __shared__ float sh_cs[WN][CP];
    __shared__ float sh_act[3][CP];       // sig(i), sig(o), tanh(g)
    __shared__ float sh_gw[3][WN][CP];    // raw f,i,g word gates
    __shared__ float sh_cwown[WN][CP];
    __shared__ float sh_alpha[WN][CP];
    __shared__ float sh_cprev[CP];
    __shared__ int   sh_mrow[WN];
    __shared__ int   sh_srow[WN];

    // ---- load this CTA's weight columns into registers ----
    float wreg[4][16];
    #pragma unroll
    for (int k = 0; k < 4; k++)
        #pragma unroll
        for (int m = 0; m < 16; m++) wreg[k][m] = 0.0f;

    if (wid < 3) {
        const float* base = U + (size_t)(wid * 512 + j0);
        #pragma unroll
        for (int m = 0; m < 16; m++) {
            int r = lane + 32 * m;
            #pragma unroll
            for (int k = 0; k < 4; k++) wreg[k][m] = base[(size_t)r * G3H + k];
        }
    } else if (wid < 6) {
        const float* base = Uw + (size_t)((wid - 3) * 512 + j0);
        #pragma unroll
        for (int m = 0; m < 16; m++) {
            int r = lane + 32 * m;
            #pragma unroll
            for (int k = 0; k < 4; k++) wreg[k][m] = base[(size_t)r * G3H + k];
        }
    } else {
        const float* base = Ua + (size_t)(j0 + (wid - 6) * 2);
        #pragma unroll
        for (int m = 0; m < 16; m++) {
            int r = lane + 32 * m;
            #pragma unroll
            for (int k = 0; k < 2; k++) wreg[k][m] = base[(size_t)r * HN + k];
        }
    }

    if (tid < CP) sh_cprev[tid] = c0[j0 + tid];

    for (int t = 0; t < TN; t++) {
        // ---- phase 0 loads (state t-1 visible via previous barrier) ----
        if (tid < WN) {
            sh_mrow[tid] = g_mask[t * WN + tid];
            sh_srow[tid] = word_starts[t * WN + tid];
        }
        {
            const float* hp = (t == 0) ? h0 : (out + (size_t)(t - 1) * (2 * HN));
            sh_h[tid]       = hp[tid];
            sh_h[tid + 256] = hp[tid + 256];
        }
        if (tid >= 64 && tid < 76) {
            int i = tid - 64;
            sh_px[i >> 2][i & 3] = g_px[(size_t)t * G3H + (i >> 2) * 512 + j0 + (i & 3)];
        } else if (tid >= 80 && tid < 80 + CP) {
            sh_pxa[tid - 80] = g_pxa[(size_t)t * HN + j0 + (tid - 80)];
        }
        __syncthreads();

        // compact active-word list (redundantly per-thread from smem)
        int na = 0;
        int wsl[WN], wst[WN];
        #pragma unroll
        for (int w = 0; w < WN; w++) {
            if (sh_mrow[w]) { wsl[na] = w; wst[na] = sh_srow[w]; na++; }
        }

        // ---- phase 1 loads (active-word operands) ----
        for (int a = 0; a < na; a++) {
            int s = wst[a];
            if (s < t) {
                const float* hsrc = out + (size_t)s * (2 * HN);
                sh_hs[a][tid]       = hsrc[tid];
                sh_hs[a][tid + 256] = hsrc[tid + 256];
            } else {
                sh_hs[a][tid] = 0.0f; sh_hs[a][tid + 256] = 0.0f;
            }
        }
        if (tid < na * CP) {
            int a = tid >> 2, k = tid & 3;
            int s = wst[a];
            sh_cs[a][k] = (s < t) ? out[(size_t)s * (2 * HN) + HN + j0 + k] : 0.0f;
        }
        if (tid >= 32 && tid < 32 + na * 12) {
            int r = tid - 32;
            int a = r / 12, i = r % 12;
            sh_pxw[a][i >> 2][i & 3] =
                g_pxw[(size_t)(t * WN + wsl[a]) * G3H + (i >> 2) * 512 + j0 + (i & 3)];
        }
        __syncthreads();

        // ---- stage 1: U and Uw matvecs (warp dot products) ----
        if (wid < 3) {
            float hr[16];
            #pragma unroll
            for (int m = 0; m < 16; m++) hr[m] = sh_h[lane + 32 * m];
            float d[4] = {0.f, 0.f, 0.f, 0.f};
            #pragma unroll
            for (int m = 0; m < 16; m++)
                #pragma unroll
                for (int k = 0; k < 4; k++) d[k] = fmaf(hr[m], wreg[k][m], d[k]);
            #pragma unroll
            for (int off = 16; off > 0; off >>= 1)
                #pragma unroll
                for (int k = 0; k < 4; k++) d[k] += __shfl_xor_sync(0xffffffffu, d[k], off);
            if (lane == 0) {
                #pragma unroll
                for (int k = 0; k < 4; k++) {
                    float v = sh_px[wid][k] + d[k];
                    sh_act[wid][k] = (wid == 2) ? tanhf(v) : sigmf(v);
                }
            }
        } else if (wid < 6) {
            int q = wid - 3;
            for (int a = 0; a < na; a++) {
                float hr[16];
                #pragma unroll
                for (int m = 0; m < 16; m++) hr[m] = sh_hs[a][lane + 32 * m];
                float d[4] = {0.f, 0.f, 0.f, 0.f};
                #pragma unroll
                for (int m = 0; m < 16; m++)
                    #pragma unroll
                    for (int k = 0; k < 4; k++) d[k] = fmaf(hr[m], wreg[k][m], d[k]);
                #pragma unroll
                for (int off = 16; off > 0; off >>= 1)
                    #pragma unroll
                    for (int k = 0; k < 4; k++) d[k] += __shfl_xor_sync(0xffffffffu, d[k], off);
                if (lane == 0) {
                    #pragma unroll
                    for (int k = 0; k < 4; k++)
                        sh_gw[q][a][k] = sh_pxw[a][q][k] + d[k];
                }
            }
        }
        __syncthreads();

        // ---- c_w (own columns) + publish to L2 ----
        if (tid < na * CP) {
            int a = tid >> 2, k = tid & 3;
            float f  = sh_gw[0][a][k];
            float iw = sh_gw[1][a][k];
            float gw = sh_gw[2][a][k];
            float cw = sigmf(f) * sh_cs[a][k] + sigmf(iw) * tanhf(gw);
            sh_cwown[a][k] = cw;
            g_cw[a * HN + j0 + k] = cw;
        }
        __threadfence();
        __syncthreads();
        // ---- grid barrier A ----
        if (tid == 0) {
            atomicAdd(&g_bar, 1);
            int target = NC * (2 * t + 1);
            while (*(volatile int*)&g_bar < target) { }
            __threadfence();
        }
        __syncthreads();

        // ---- read full c_w, stage 2: Ua matvec -> alpha ----
        for (int a = 0; a < na; a++) {
            sh_cw[a][tid]       = g_cw[a * HN + tid];
            sh_cw[a][tid + 256] = g_cw[a * HN + tid + 256];
        }
        __syncthreads();

        if (wid >= 6 && na > 0) {
            int kb = (wid - 6) * 2;
            for (int a = 0; a < na; a++) {
                float cr[16];
                #pragma unroll
                for (int m = 0; m < 16; m++) cr[m] = sh_cw[a][lane + 32 * m];
                float d[2] = {0.f, 0.f};
                #pragma unroll
                for (int m = 0; m < 16; m++)
                    #pragma unroll
                    for (int k = 0; k < 2; k++) d[k] = fmaf(cr[m], wreg[k][m], d[k]);
                #pragma unroll
                for (int off = 16; off > 0; off >>= 1)
                    #pragma unroll
                    for (int k = 0; k < 2; k++) d[k] += __shfl_xor_sync(0xffffffffu, d[k], off);
                if (lane == 0) {
                    #pragma unroll
                    for (int k = 0; k < 2; k++)
                        sh_alpha[a][kb + k] = sigmf(sh_pxa[kb + k] + d[k]);
                }
            }
        }
        __syncthreads();

        // ---- combine, write h_t / c_t ----
        if (tid < CP) {
            int k = tid;
            float ig = sh_act[0][k], og = sh_act[1][k], gg = sh_act[2][k];
            float c1;
            if (na > 0) {
                float e0 = expf(ig);
                float den = e0, num = e0 * gg;
                for (int a = 0; a < na; a++) {
                    float ea = expf(sh_alpha[a][k]);
                    den += ea;
                    num = fmaf(ea, sh_cwown[a][k], num);
                }
                c1 = num / den;
            } else {
                c1 = (1.0f - ig) * sh_cprev[k] + ig * gg;
            }
            float h1 = og * tanhf(c1);
            sh_cprev[k] = c1;
            out[(size_t)t * (2 * HN) + j0 + k]      = h1;
            out[(size_t)t * (2 * HN) + HN + j0 + k] = c1;
        }
        __threadfence();
        __syncthreads();
        // ---- grid barrier B ----
        if (tid == 0) {
            atomicAdd(&g_bar, 1);
            int target = NC * (2 * t + 2);
            while (*(volatile int*)&g_bar < target) { }
            __threadfence();
        }
        __syncthreads();
    }
}

// ---------------- launch ----------------
extern "C" void kernel_launch(void* const* d_in, const int* in_sizes, int n_in,
                              void* d_out, int out_size)
{
    const float*         x     = (const float*)d_in[0];
    const int*           wids  = (const int*)d_in[1];
    const int*           wst   = (const int*)d_in[2];
    const unsigned char* wmask = (const unsigned char*)d_in[3];
    const float*         h0    = (const float*)d_in[4];
    const float*         c0    = (const float*)d_in[5];
    const float*         emb   = (const float*)d_in[6];
    const float*         W     = (const float*)d_in[7];
    const float*         U     = (const float*)d_in[8];
    const float*         b     = (const float*)d_in[9];
    const float*         Wa    = (const float*)d_in[10];
    const float*         Ua    = (const float*)d_in[11];
    const float*         ba    = (const float*)d_in[12];
    const float*         Ww    = (const float*)d_in[13];
    const float*         Uw    = (const float*)d_in[14];
    const float*         bw    = (const float*)d_in[15];
    float*               out   = (float*)d_out;

    zero_kernel<<<1, 1>>>();
    mask_decode_kernel<<<1, 256>>>(wmask);
    build_active_kernel<<<(TN * WN + 255) / 256, 256>>>(wids);

    // px = x @ W + b          [4096 x 1536], K=128
    sgemm_kernel<<<dim3(G3H / 64, TN / 64), 256>>>(x, W, b, TN, G3H, DN, 0, 0);
    // pxa = x @ Wa + ba       [4096 x 512], K=128
    sgemm_kernel<<<dim3(HN / 64, TN / 64), 256>>>(x, Wa, ba, TN, HN, DN, 0, 1);
    // pxw = emb[gather] @ Ww + bw, scattered to (t*WN+w) rows, K=256
    sgemm_kernel<<<dim3(G3H / 64, (TN * WN) / 64), 256>>>(emb, Ww, bw, TN * WN, G3H, EN, 1, 2);

    scan_kernel<<<NC, NTH>>>(h0, c0, wst, U, Uw, Ua, out);
}